// round 1
// baseline (speedup 1.0000x reference)
#include <cuda_runtime.h>
#include <math.h>

#define NACC_MAX 200000
#define NMER_MAX 100000

// ---------------- scratch (device globals; no allocations allowed) -------------
__device__ float g_xa[(size_t)NACC_MAX * 128];   // account features (current)
__device__ float g_xm[(size_t)NMER_MAX * 128];   // merchant features (current)
__device__ float g_ya[(size_t)NACC_MAX * 128];   // pre-BN account accum
__device__ float g_ym[(size_t)NMER_MAX * 128];   // pre-BN merchant
__device__ float g_agg[(size_t)NACC_MAX * 128];  // segment-sum scratch
__device__ float g_cnt[NACC_MAX];                // segment counts
__device__ float g_wt[256 * 128];                // transposed weight panel [K][DOUT]
__device__ float g_sum[128];
__device__ float g_sqs[128];

// ---------------- edge aggregation: warp per edge ------------------------------
__global__ __launch_bounds__(256)
void edge_agg_kernel(const int* __restrict__ ei, int E,
                     const float* __restrict__ xsrc,
                     float* __restrict__ agg, float* __restrict__ cnt)
{
    int gw = (blockIdx.x * blockDim.x + threadIdx.x) >> 5;
    int lane = threadIdx.x & 31;
    if (gw >= E) return;
    int src = __ldg(&ei[gw]);
    int dst = __ldg(&ei[E + gw]);
    float4 v = __ldg(reinterpret_cast<const float4*>(xsrc + (size_t)src * 128) + lane);
    float* daddr = agg + (size_t)dst * 128 + lane * 4;
    asm volatile("red.global.add.v4.f32 [%0], {%1, %2, %3, %4};"
                 :: "l"(daddr), "f"(v.x), "f"(v.y), "f"(v.z), "f"(v.w) : "memory");
    if (lane == 0)
        asm volatile("red.global.add.f32 [%0], %1;"
                     :: "l"(cnt + dst), "f"(1.0f) : "memory");
}

// ---------------- weight transpose: Wt[k][j] = k<K1 ? W1[j][k] : W2[j][k-K1] ----
__global__ void transpose_wt(const float* __restrict__ W1, const float* __restrict__ W2,
                             float* __restrict__ out, int K1, int K2, int dout)
{
    int idx = blockIdx.x * blockDim.x + threadIdx.x;
    int K = K1 + K2;
    if (idx >= K * dout) return;
    int k = idx / dout, j = idx % dout;
    out[idx] = (k < K1) ? W1[(size_t)j * K1 + k] : W2[(size_t)j * K2 + (k - K1)];
}

// ---------------- fused GEMM ---------------------------------------------------
// MODE 0: C = A1[n,K] @ Wt + bias                      (input projection)
// MODE 1: C = [mean | xdst][n,256] @ Wt + bias, row-L2-normalized; mean folded
//         into A-load via 1/max(cnt,1). ACCUM: C += result (HeteroConv sum).
// Tile: BM=64 rows x DOUT cols, BK=32, 256 threads, thread tile 8 rows x CN cols.
#define BM 64
#define BK 32

template<int DOUT, int MODE, bool ACCUM>
__global__ __launch_bounds__(256)
void gemm_kernel(int n, int K,
                 const float* __restrict__ A1,
                 const float* __restrict__ A2,
                 const float* __restrict__ cnt,
                 const float* __restrict__ Wt,
                 const float* __restrict__ bias,
                 float* __restrict__ C)
{
    constexpr int CN = DOUT / 32;
    __shared__ float As[BM][BK + 4];
    __shared__ float Bs[BK][DOUT];
    __shared__ float sInv[BM];

    int tid = threadIdx.x;
    int warp = tid >> 5, lane = tid & 31;
    int row0 = blockIdx.x * BM;

    if (MODE == 1 && tid < BM) {
        int r = row0 + tid;
        float c = (r < n) ? cnt[r] : 1.f;
        sInv[tid] = 1.f / fmaxf(c, 1.f);
    }
    __syncthreads();

    float acc[8][CN];
#pragma unroll
    for (int i = 0; i < 8; i++)
#pragma unroll
        for (int c = 0; c < CN; c++) acc[i][c] = 0.f;

    for (int k0 = 0; k0 < K; k0 += BK) {
        // A tile: 64x32, 512 float4, 2 per thread, coalesced
#pragma unroll
        for (int i = 0; i < 2; i++) {
            int idx = tid + i * 256;
            int m = idx >> 3;
            int kq = (idx & 7) * 4;
            int r = row0 + m;
            int kk = k0 + kq;
            float4 v = make_float4(0.f, 0.f, 0.f, 0.f);
            if (r < n) {
                if (MODE == 0) {
                    v = *reinterpret_cast<const float4*>(A1 + (size_t)r * K + kk);
                } else {
                    if (kk < 128) {
                        v = *reinterpret_cast<const float4*>(A1 + (size_t)r * 128 + kk);
                        float s = sInv[m];
                        v.x *= s; v.y *= s; v.z *= s; v.w *= s;
                    } else {
                        v = *reinterpret_cast<const float4*>(A2 + (size_t)r * 128 + (kk - 128));
                    }
                }
            }
            As[m][kq + 0] = v.x; As[m][kq + 1] = v.y;
            As[m][kq + 2] = v.z; As[m][kq + 3] = v.w;
        }
        // B tile: BK x DOUT, already transposed in global, straight copy
#pragma unroll
        for (int i = 0; i < (BK * DOUT) / (4 * 256); i++) {
            int idx = tid + i * 256;
            int kk = idx / (DOUT / 4);
            int jq = (idx % (DOUT / 4)) * 4;
            float4 v = *reinterpret_cast<const float4*>(Wt + (size_t)(k0 + kk) * DOUT + jq);
            *reinterpret_cast<float4*>(&Bs[kk][jq]) = v;
        }
        __syncthreads();

        int r0 = warp * 8;
#pragma unroll
        for (int k = 0; k < BK; k += 4) {
            float4 a[8];
#pragma unroll
            for (int r = 0; r < 8; r++)
                a[r] = *reinterpret_cast<const float4*>(&As[r0 + r][k]);
#pragma unroll
            for (int kk2 = 0; kk2 < 4; kk2++) {
                float b[CN];
#pragma unroll
                for (int c = 0; c < CN; c++) b[c] = Bs[k + kk2][lane * CN + c];
#pragma unroll
                for (int r = 0; r < 8; r++) {
                    float av = (kk2 == 0) ? a[r].x : (kk2 == 1) ? a[r].y
                             : (kk2 == 2) ? a[r].z : a[r].w;
#pragma unroll
                    for (int c = 0; c < CN; c++) acc[r][c] += av * b[c];
                }
            }
        }
        __syncthreads();
    }

    float bv[CN];
#pragma unroll
    for (int c = 0; c < CN; c++) bv[c] = __ldg(&bias[lane * CN + c]);

    int r0 = warp * 8;
#pragma unroll
    for (int r = 0; r < 8; r++) {
        int row = row0 + r0 + r;
        float v[CN];
#pragma unroll
        for (int c = 0; c < CN; c++) v[c] = acc[r][c] + bv[c];
        if (MODE == 1) {
            float ss = 0.f;
#pragma unroll
            for (int c = 0; c < CN; c++) ss += v[c] * v[c];
#pragma unroll
            for (int off = 16; off; off >>= 1)
                ss += __shfl_xor_sync(0xffffffffu, ss, off);
            float s = 1.f / fmaxf(sqrtf(ss), 1e-12f);
#pragma unroll
            for (int c = 0; c < CN; c++) v[c] *= s;
        }
        if (row < n) {
            float* cp = C + (size_t)row * DOUT + lane * CN;
            if (ACCUM) {
#pragma unroll
                for (int c = 0; c < CN; c++) v[c] += cp[c];
            }
#pragma unroll
            for (int c = 0; c < CN; c++) cp[c] = v[c];
        }
    }
}

// ---------------- BatchNorm (training mode, batch stats) -----------------------
__global__ void bn_stats_kernel(const float* __restrict__ X, int n,
                                float* __restrict__ sum, float* __restrict__ sqs)
{
    int d = blockDim.x;
    int c = threadIdx.x;
    float s = 0.f, q = 0.f;
    for (int r = blockIdx.x; r < n; r += gridDim.x) {
        float v = X[(size_t)r * d + c];
        s += v; q += v * v;
    }
    atomicAdd(&sum[c], s);
    atomicAdd(&sqs[c], q);
}

__global__ void bn_apply_kernel(const float* __restrict__ X, float* __restrict__ Y,
                                int n, int d,
                                const float* __restrict__ sum, const float* __restrict__ sqs,
                                const float* __restrict__ g, const float* __restrict__ b,
                                int relu)
{
    size_t total = (size_t)n * d;
    float invn = 1.f / (float)n;
    for (size_t i = blockIdx.x * (size_t)blockDim.x + threadIdx.x; i < total;
         i += (size_t)gridDim.x * blockDim.x) {
        int c = (int)(i % d);
        float mu = sum[c] * invn;
        float var = sqs[c] * invn - mu * mu;
        float y = (X[i] - mu) * rsqrtf(var + 1e-5f) * g[c] + b[c];
        if (relu) y = fmaxf(y, 0.f);
        Y[i] = y;
    }
}

// ---------------- fused classifier: relu(x@W1^T+b1)@W2^T+b2 --------------------
__global__ __launch_bounds__(256)
void classifier_kernel(const float* __restrict__ X, int n,
                       const float* __restrict__ W1, const float* __restrict__ b1,
                       const float* __restrict__ W2, const float* __restrict__ b2,
                       float* __restrict__ out)
{
    __shared__ float sW1[64 * 65];
    __shared__ float sW2[64];
    __shared__ float sb1[64];
    int tid = threadIdx.x;
    for (int i = tid; i < 64 * 64; i += 256) {
        int j = i >> 6, k = i & 63;
        sW1[j * 65 + k] = W1[i];
    }
    if (tid < 64) { sW2[tid] = W2[tid]; sb1[tid] = b1[tid]; }
    __syncthreads();

    int lane = tid & 31;
    int row = blockIdx.x * 8 + (tid >> 5);
    if (row >= n) return;
    float x0 = X[(size_t)row * 64 + lane];
    float x1 = X[(size_t)row * 64 + 32 + lane];
    float h0 = sb1[lane], h1 = sb1[lane + 32];
#pragma unroll
    for (int k = 0; k < 32; k++) {
        float xk = __shfl_sync(0xffffffffu, x0, k);
        h0 += xk * sW1[lane * 65 + k];
        h1 += xk * sW1[(lane + 32) * 65 + k];
    }
#pragma unroll
    for (int k = 0; k < 32; k++) {
        float xk = __shfl_sync(0xffffffffu, x1, k);
        h0 += xk * sW1[lane * 65 + 32 + k];
        h1 += xk * sW1[(lane + 32) * 65 + 32 + k];
    }
    h0 = fmaxf(h0, 0.f); h1 = fmaxf(h1, 0.f);
    float p = h0 * sW2[lane] + h1 * sW2[lane + 32];
#pragma unroll
    for (int off = 16; off; off >>= 1)
        p += __shfl_xor_sync(0xffffffffu, p, off);
    if (lane == 0) out[row] = p + b2[0];
}

// ---------------- dispatch helper ----------------------------------------------
static void launch_sage_gemm(int DO, bool accum, int n,
                             const float* agg, const float* xd, const float* cnt,
                             const float* wt, const float* bias, float* C)
{
    int blocks = (n + BM - 1) / BM;
    if (DO == 128) {
        if (accum) gemm_kernel<128, 1, true ><<<blocks, 256>>>(n, 256, agg, xd, cnt, wt, bias, C);
        else       gemm_kernel<128, 1, false><<<blocks, 256>>>(n, 256, agg, xd, cnt, wt, bias, C);
    } else {
        if (accum) gemm_kernel<64, 1, true ><<<blocks, 256>>>(n, 256, agg, xd, cnt, wt, bias, C);
        else       gemm_kernel<64, 1, false><<<blocks, 256>>>(n, 256, agg, xd, cnt, wt, bias, C);
    }
}

// ---------------- kernel_launch -------------------------------------------------
extern "C" void kernel_launch(void* const* d_in, const int* in_sizes, int n_in,
                              void* d_out, int out_size)
{
    const float* x_acc      = (const float*)d_in[0];
    const float* x_mer      = (const float*)d_in[1];
    const int*   ei_pays    = (const int*)d_in[2];
    const int*   ei_rev     = (const int*)d_in[3];
    const int*   ei_tr      = (const int*)d_in[4];
    const float* projW_acc  = (const float*)d_in[5];
    const float* projb_acc  = (const float*)d_in[6];
    const float* projW_mer  = (const float*)d_in[7];
    const float* projb_mer  = (const float*)d_in[8];
    const float* Wl[3] = {(const float*)d_in[9],  (const float*)d_in[12], (const float*)d_in[15]};
    const float* bl[3] = {(const float*)d_in[10], (const float*)d_in[13], (const float*)d_in[16]};
    const float* Wr[3] = {(const float*)d_in[11], (const float*)d_in[14], (const float*)d_in[17]};
    const float* bng[3] = {(const float*)d_in[18], (const float*)d_in[20], (const float*)d_in[22]};
    const float* bnb[3] = {(const float*)d_in[19], (const float*)d_in[21], (const float*)d_in[23]};
    const float* clfW1 = (const float*)d_in[24];
    const float* clfb1 = (const float*)d_in[25];
    const float* clfW2 = (const float*)d_in[26];
    const float* clfb2 = (const float*)d_in[27];
    float* out = (float*)d_out;

    int nacc = in_sizes[0] / 64;
    int nmer = in_sizes[1] / 32;
    int E    = in_sizes[2] / 2;

    float *xa, *xm, *ya, *ym, *agg, *cnt, *wt, *gsum, *gsqs;
    cudaGetSymbolAddress((void**)&xa,   g_xa);
    cudaGetSymbolAddress((void**)&xm,   g_xm);
    cudaGetSymbolAddress((void**)&ya,   g_ya);
    cudaGetSymbolAddress((void**)&ym,   g_ym);
    cudaGetSymbolAddress((void**)&agg,  g_agg);
    cudaGetSymbolAddress((void**)&cnt,  g_cnt);
    cudaGetSymbolAddress((void**)&wt,   g_wt);
    cudaGetSymbolAddress((void**)&gsum, g_sum);
    cudaGetSymbolAddress((void**)&gsqs, g_sqs);

    int ablocks = (nacc + BM - 1) / BM;
    int mblocks = (nmer + BM - 1) / BM;
    int eblocks = (E + 7) / 8;

    // --- input projections ---
    transpose_wt<<<(64 * 128 + 255) / 256, 256>>>(projW_acc, nullptr, wt, 64, 0, 128);
    gemm_kernel<128, 0, false><<<ablocks, 256>>>(nacc, 64, x_acc, nullptr, nullptr, wt, projb_acc, xa);
    transpose_wt<<<(32 * 128 + 255) / 256, 256>>>(projW_mer, nullptr, wt, 32, 0, 128);
    gemm_kernel<128, 0, false><<<mblocks, 256>>>(nmer, 32, x_mer, nullptr, nullptr, wt, projb_mer, xm);

    int douts[3] = {128, 128, 64};
    for (int L = 0; L < 3; L++) {
        int DO = douts[L];

        // (a) pays: acc -> mer. Dead at L==2 (merchant output unused).
        if (L < 2) {
            cudaMemsetAsync(agg, 0, (size_t)nmer * 128 * sizeof(float), 0);
            cudaMemsetAsync(cnt, 0, (size_t)nmer * sizeof(float), 0);
            edge_agg_kernel<<<eblocks, 256>>>(ei_pays, E, xa, agg, cnt);
            transpose_wt<<<(256 * DO + 255) / 256, 256>>>(Wl[L] + 0 * (size_t)DO * 128,
                                                          Wr[L] + 0 * (size_t)DO * 128,
                                                          wt, 128, 128, DO);
            launch_sage_gemm(DO, false, nmer, agg, xm, cnt, wt, bl[L] + 0 * DO, ym);
        }

        // (b) rev: mer -> acc
        cudaMemsetAsync(agg, 0, (size_t)nacc * 128 * sizeof(float), 0);
        cudaMemsetAsync(cnt, 0, (size_t)nacc * sizeof(float), 0);
        edge_agg_kernel<<<eblocks, 256>>>(ei_rev, E, xm, agg, cnt);
        transpose_wt<<<(256 * DO + 255) / 256, 256>>>(Wl[L] + 1 * (size_t)DO * 128,
                                                      Wr[L] + 1 * (size_t)DO * 128,
                                                      wt, 128, 128, DO);
        launch_sage_gemm(DO, false, nacc, agg, xa, cnt, wt, bl[L] + 1 * DO, ya);

        // (c) transfer: acc -> acc (accumulate: HeteroConv sum)
        cudaMemsetAsync(agg, 0, (size_t)nacc * 128 * sizeof(float), 0);
        cudaMemsetAsync(cnt, 0, (size_t)nacc * sizeof(float), 0);
        edge_agg_kernel<<<eblocks, 256>>>(ei_tr, E, xa, agg, cnt);
        transpose_wt<<<(256 * DO + 255) / 256, 256>>>(Wl[L] + 2 * (size_t)DO * 128,
                                                      Wr[L] + 2 * (size_t)DO * 128,
                                                      wt, 128, 128, DO);
        launch_sage_gemm(DO, true, nacc, agg, xa, cnt, wt, bl[L] + 2 * DO, ya);

        // (d) BN account (+ReLU except last layer)
        cudaMemsetAsync(gsum, 0, DO * sizeof(float), 0);
        cudaMemsetAsync(gsqs, 0, DO * sizeof(float), 0);
        bn_stats_kernel<<<512, DO>>>(ya, nacc, gsum, gsqs);
        bn_apply_kernel<<<2048, 256>>>(ya, xa, nacc, DO, gsum, gsqs,
                                       bng[L] + 0 * DO, bnb[L] + 0 * DO, (L < 2) ? 1 : 0);

        // (e) BN merchant (+ReLU). Dead at L==2.
        if (L < 2) {
            cudaMemsetAsync(gsum, 0, DO * sizeof(float), 0);
            cudaMemsetAsync(gsqs, 0, DO * sizeof(float), 0);
            bn_stats_kernel<<<512, DO>>>(ym, nmer, gsum, gsqs);
            bn_apply_kernel<<<2048, 256>>>(ym, xm, nmer, DO, gsum, gsqs,
                                           bng[L] + 1 * DO, bnb[L] + 1 * DO, 1);
        }
    }

    // --- classifier head on accounts ---
    classifier_kernel<<<(nacc + 7) / 8, 256>>>(xa, nacc, clfW1, clfb1, clfW2, clfb2, out);
}

// round 3
// speedup vs baseline: 1.3423x; 1.3423x over previous
#include <cuda_runtime.h>
#include <math.h>
#include <stdint.h>

#define NACC_MAX 200000
#define NMER_MAX 100000

// ---------------- scratch (device globals; no allocations allowed) -------------
__device__ float g_xa[(size_t)NACC_MAX * 128];   // account features (current)
__device__ float g_xm[(size_t)NMER_MAX * 128];   // merchant features (current)
__device__ float g_ya[(size_t)NACC_MAX * 128];   // pre-BN account accum
__device__ float g_ym[(size_t)NMER_MAX * 128];   // pre-BN merchant
__device__ float g_agg[(size_t)NACC_MAX * 128];  // segment-sum scratch
__device__ float g_cnt[NACC_MAX];                // segment counts
__device__ float g_sum[128];
__device__ float g_sqs[128];

// ---------------- helpers --------------------------------------------------------
__device__ __forceinline__ float tf32r(float x) {
    uint32_t u;
    asm("cvt.rna.tf32.f32 %0, %1;" : "=r"(u) : "f"(x));
    return __uint_as_float(u);
}

__device__ __forceinline__ void mma_tf32(float* d, const uint32_t* a,
                                         uint32_t b0, uint32_t b1) {
    asm volatile(
        "mma.sync.aligned.m16n8k8.row.col.f32.tf32.tf32.f32 "
        "{%0,%1,%2,%3}, {%4,%5,%6,%7}, {%8,%9}, {%0,%1,%2,%3};"
        : "+f"(d[0]), "+f"(d[1]), "+f"(d[2]), "+f"(d[3])
        : "r"(a[0]), "r"(a[1]), "r"(a[2]), "r"(a[3]), "r"(b0), "r"(b1));
}

// ---------------- edge aggregation: warp per edge ------------------------------
__global__ __launch_bounds__(256)
void edge_agg_kernel(const int* __restrict__ ei, int E,
                     const float* __restrict__ xsrc,
                     float* __restrict__ agg, float* __restrict__ cnt)
{
    int gw = (blockIdx.x * blockDim.x + threadIdx.x) >> 5;
    int lane = threadIdx.x & 31;
    if (gw >= E) return;
    int src = __ldg(&ei[gw]);
    int dst = __ldg(&ei[E + gw]);
    float4 v = __ldg(reinterpret_cast<const float4*>(xsrc + (size_t)src * 128) + lane);
    float* daddr = agg + (size_t)dst * 128 + lane * 4;
    asm volatile("red.global.add.v4.f32 [%0], {%1, %2, %3, %4};"
                 :: "l"(daddr), "f"(v.x), "f"(v.y), "f"(v.z), "f"(v.w) : "memory");
    if (lane == 0)
        asm volatile("red.global.add.f32 [%0], %1;"
                     :: "l"(cnt + dst), "f"(1.0f) : "memory");
}

// ---------------- tf32 mma.sync GEMM ---------------------------------------------
// D[128, DO] per CTA = A[128, K] @ B[DO, K]^T   (W row-major [DO,K] is the K-major
// "col" operand of mma.m16n8k8 directly -- no transpose needed).
// MODE 0: A = A1[n,K] (input projection), epilogue = +bias.
// MODE 1: K=256, A = [agg*inv(cnt) | xdst], B = [Wl | Wr] along K,
//         epilogue = +bias, row L2-normalize, optional += into C.
// 256 threads = 8 warps tiled 2(m) x 4(n); warp tile 64m x (DO/4)n.
template<int DO, int MODE, bool ACCUM>
__global__ __launch_bounds__(256)
void mma_gemm(int n, int K,
              const float* __restrict__ A1, const float* __restrict__ A2,
              const float* __restrict__ cnt,
              const float* __restrict__ B1, const float* __restrict__ B2,
              const float* __restrict__ bias,
              float* __restrict__ C)
{
    constexpr int NJ = DO / 32;          // j-tiles (of 8 cols) per warp
    __shared__ float As[128][36];
    __shared__ float Bs[DO][36];
    __shared__ float sInv[128];
    __shared__ float sBias[DO];
    __shared__ float ssRow[128];

    int tid = threadIdx.x;
    int lane = tid & 31, warp = tid >> 5;
    int g = lane >> 2, t = lane & 3;
    int wm = warp & 1, wn = warp >> 1;   // 2 x 4 warp grid
    int row0 = blockIdx.x * 128;

    if (tid < DO) sBias[tid] = bias[tid];
    if (tid < 128) {
        if (MODE == 1) {
            int r = row0 + tid;
            sInv[tid] = 1.f / fmaxf((r < n) ? cnt[r] : 1.f, 1.f);
        }
        ssRow[tid] = 0.f;
    }

    float acc[4][NJ][4];
#pragma unroll
    for (int i = 0; i < 4; i++)
#pragma unroll
        for (int j = 0; j < NJ; j++)
#pragma unroll
            for (int c = 0; c < 4; c++) acc[i][j][c] = 0.f;

    for (int k0 = 0; k0 < K; k0 += 32) {
        __syncthreads();
        // ---- A tile: 128 x 32, tf32-rounded ----
#pragma unroll
        for (int i = 0; i < 4; i++) {
            int idx = tid + i * 256;
            int m = idx >> 3, q = idx & 7;
            int r = row0 + m, k = k0 + q * 4;
            float4 a = make_float4(0.f, 0.f, 0.f, 0.f);
            if (r < n) {
                if (MODE == 0) {
                    a = __ldg(reinterpret_cast<const float4*>(A1 + (size_t)r * K + k));
                } else if (k < 128) {
                    a = __ldg(reinterpret_cast<const float4*>(A1 + (size_t)r * 128 + k));
                    float si = sInv[m];
                    a.x *= si; a.y *= si; a.z *= si; a.w *= si;
                } else {
                    a = __ldg(reinterpret_cast<const float4*>(A2 + (size_t)r * 128 + (k - 128)));
                }
            }
            *reinterpret_cast<float4*>(&As[m][q * 4]) =
                make_float4(tf32r(a.x), tf32r(a.y), tf32r(a.z), tf32r(a.w));
        }
        // ---- B tile: DO x 32, straight rows of W ----
#pragma unroll
        for (int i = 0; i < (DO * 8) / 256; i++) {
            int idx = tid + i * 256;
            int j = idx >> 3, q = idx & 7;
            int k = k0 + q * 4;
            float4 w;
            if (MODE == 1) {
                w = (k < 128)
                  ? __ldg(reinterpret_cast<const float4*>(B1 + (size_t)j * 128 + k))
                  : __ldg(reinterpret_cast<const float4*>(B2 + (size_t)j * 128 + (k - 128)));
            } else {
                w = __ldg(reinterpret_cast<const float4*>(B1 + (size_t)j * K + k));
            }
            *reinterpret_cast<float4*>(&Bs[j][q * 4]) =
                make_float4(tf32r(w.x), tf32r(w.y), tf32r(w.z), tf32r(w.w));
        }
        __syncthreads();

        // ---- compute: 4 k-steps of 8 ----
#pragma unroll
        for (int ks = 0; ks < 32; ks += 8) {
            uint32_t a[4][4];
#pragma unroll
            for (int i = 0; i < 4; i++) {
                int rb = wm * 64 + i * 16;
                a[i][0] = __float_as_uint(As[rb + g][ks + t]);
                a[i][1] = __float_as_uint(As[rb + g + 8][ks + t]);
                a[i][2] = __float_as_uint(As[rb + g][ks + t + 4]);
                a[i][3] = __float_as_uint(As[rb + g + 8][ks + t + 4]);
            }
#pragma unroll
            for (int j = 0; j < NJ; j++) {
                int nb = wn * (NJ * 8) + j * 8 + g;
                uint32_t b0 = __float_as_uint(Bs[nb][ks + t]);
                uint32_t b1 = __float_as_uint(Bs[nb][ks + t + 4]);
#pragma unroll
                for (int i = 0; i < 4; i++) mma_tf32(acc[i][j], a[i], b0, b1);
            }
        }
    }

    // ---- epilogue: bias, L2 row-norm (cross-warp via smem atomics), store ----
#pragma unroll
    for (int i = 0; i < 4; i++) {
        float ss0 = 0.f, ss1 = 0.f;
#pragma unroll
        for (int j = 0; j < NJ; j++) {
            int cb = wn * (NJ * 8) + j * 8 + t * 2;
            float bv0 = sBias[cb], bv1 = sBias[cb + 1];
            acc[i][j][0] += bv0; acc[i][j][1] += bv1;
            acc[i][j][2] += bv0; acc[i][j][3] += bv1;
            if (MODE == 1) {
                ss0 += acc[i][j][0] * acc[i][j][0] + acc[i][j][1] * acc[i][j][1];
                ss1 += acc[i][j][2] * acc[i][j][2] + acc[i][j][3] * acc[i][j][3];
            }
        }
        if (MODE == 1) {
            ss0 += __shfl_xor_sync(0xffffffffu, ss0, 1);
            ss0 += __shfl_xor_sync(0xffffffffu, ss0, 2);
            ss1 += __shfl_xor_sync(0xffffffffu, ss1, 1);
            ss1 += __shfl_xor_sync(0xffffffffu, ss1, 2);
            if (t == 0) {
                atomicAdd(&ssRow[wm * 64 + i * 16 + g], ss0);
                atomicAdd(&ssRow[wm * 64 + i * 16 + g + 8], ss1);
            }
        }
    }
    __syncthreads();

#pragma unroll
    for (int i = 0; i < 4; i++) {
        int rl = wm * 64 + i * 16 + g;
        float s0 = 1.f, s1 = 1.f;
        if (MODE == 1) {
            s0 = 1.f / fmaxf(sqrtf(ssRow[rl]), 1e-12f);
            s1 = 1.f / fmaxf(sqrtf(ssRow[rl + 8]), 1e-12f);
        }
        int r0 = row0 + rl, r1 = r0 + 8;
#pragma unroll
        for (int j = 0; j < NJ; j++) {
            int cb = wn * (NJ * 8) + j * 8 + t * 2;
            if (r0 < n) {
                float2* p = reinterpret_cast<float2*>(C + (size_t)r0 * DO + cb);
                float2 v = make_float2(acc[i][j][0] * s0, acc[i][j][1] * s0);
                if (ACCUM) { float2 o = *p; v.x += o.x; v.y += o.y; }
                *p = v;
            }
            if (r1 < n) {
                float2* p = reinterpret_cast<float2*>(C + (size_t)r1 * DO + cb);
                float2 v = make_float2(acc[i][j][2] * s1, acc[i][j][3] * s1);
                if (ACCUM) { float2 o = *p; v.x += o.x; v.y += o.y; }
                *p = v;
            }
        }
    }
}

// ---------------- BatchNorm (training mode, batch stats) -----------------------
__global__ void bn_stats_kernel(const float* __restrict__ X, int n,
                                float* __restrict__ sum, float* __restrict__ sqs)
{
    int d = blockDim.x;
    int c = threadIdx.x;
    float s = 0.f, q = 0.f;
    for (int r = blockIdx.x; r < n; r += gridDim.x) {
        float v = X[(size_t)r * d + c];
        s += v; q += v * v;
    }
    atomicAdd(&sum[c], s);
    atomicAdd(&sqs[c], q);
}

__global__ void bn_apply_kernel(const float* __restrict__ X, float* __restrict__ Y,
                                int n, int d,
                                const float* __restrict__ sum, const float* __restrict__ sqs,
                                const float* __restrict__ g, const float* __restrict__ b,
                                int relu)
{
    size_t total = (size_t)n * d;
    float invn = 1.f / (float)n;
    for (size_t i = blockIdx.x * (size_t)blockDim.x + threadIdx.x; i < total;
         i += (size_t)gridDim.x * blockDim.x) {
        int c = (int)(i % d);
        float mu = sum[c] * invn;
        float var = sqs[c] * invn - mu * mu;
        float y = (X[i] - mu) * rsqrtf(var + 1e-5f) * g[c] + b[c];
        if (relu) y = fmaxf(y, 0.f);
        Y[i] = y;
    }
}

// ---------------- fused classifier: relu(x@W1^T+b1)@W2^T+b2 --------------------
__global__ __launch_bounds__(256)
void classifier_kernel(const float* __restrict__ X, int n,
                       const float* __restrict__ W1, const float* __restrict__ b1,
                       const float* __restrict__ W2, const float* __restrict__ b2,
                       float* __restrict__ out)
{
    __shared__ float sW1[64 * 65];
    __shared__ float sW2[64];
    __shared__ float sb1[64];
    int tid = threadIdx.x;
    for (int i = tid; i < 64 * 64; i += 256) {
        int j = i >> 6, k = i & 63;
        sW1[j * 65 + k] = W1[i];
    }
    if (tid < 64) { sW2[tid] = W2[tid]; sb1[tid] = b1[tid]; }
    __syncthreads();

    int lane = tid & 31;
    int row = blockIdx.x * 8 + (tid >> 5);
    if (row >= n) return;
    float x0 = X[(size_t)row * 64 + lane];
    float x1 = X[(size_t)row * 64 + 32 + lane];
    float h0 = sb1[lane], h1 = sb1[lane + 32];
#pragma unroll
    for (int k = 0; k < 32; k++) {
        float xk = __shfl_sync(0xffffffffu, x0, k);
        h0 += xk * sW1[lane * 65 + k];
        h1 += xk * sW1[(lane + 32) * 65 + k];
    }
#pragma unroll
    for (int k = 0; k < 32; k++) {
        float xk = __shfl_sync(0xffffffffu, x1, k);
        h0 += xk * sW1[lane * 65 + 32 + k];
        h1 += xk * sW1[(lane + 32) * 65 + 32 + k];
    }
    h0 = fmaxf(h0, 0.f); h1 = fmaxf(h1, 0.f);
    float p = h0 * sW2[lane] + h1 * sW2[lane + 32];
#pragma unroll
    for (int off = 16; off; off >>= 1)
        p += __shfl_xor_sync(0xffffffffu, p, off);
    if (lane == 0) out[row] = p + b2[0];
}

// ---------------- kernel_launch -------------------------------------------------
template<int DO, bool ACC>
static void launch_sage(int n, const float* agg, const float* xd, const float* cnt,
                        const float* Wl, const float* Wr, const float* bias, float* C)
{
    mma_gemm<DO, 1, ACC><<<(n + 127) / 128, 256>>>(n, 256, agg, xd, cnt, Wl, Wr, bias, C);
}

extern "C" void kernel_launch(void* const* d_in, const int* in_sizes, int n_in,
                              void* d_out, int out_size)
{
    const float* x_acc      = (const float*)d_in[0];
    const float* x_mer      = (const float*)d_in[1];
    const int*   ei_pays    = (const int*)d_in[2];
    const int*   ei_rev     = (const int*)d_in[3];
    const int*   ei_tr      = (const int*)d_in[4];
    const float* projW_acc  = (const float*)d_in[5];
    const float* projb_acc  = (const float*)d_in[6];
    const float* projW_mer  = (const float*)d_in[7];
    const float* projb_mer  = (const float*)d_in[8];
    const float* Wl[3] = {(const float*)d_in[9],  (const float*)d_in[12], (const float*)d_in[15]};
    const float* bl[3] = {(const float*)d_in[10], (const float*)d_in[13], (const float*)d_in[16]};
    const float* Wr[3] = {(const float*)d_in[11], (const float*)d_in[14], (const float*)d_in[17]};
    const float* bng[3] = {(const float*)d_in[18], (const float*)d_in[20], (const float*)d_in[22]};
    const float* bnb[3] = {(const float*)d_in[19], (const float*)d_in[21], (const float*)d_in[23]};
    const float* clfW1 = (const float*)d_in[24];
    const float* clfb1 = (const float*)d_in[25];
    const float* clfW2 = (const float*)d_in[26];
    const float* clfb2 = (const float*)d_in[27];
    float* out = (float*)d_out;

    int nacc = in_sizes[0] / 64;
    int nmer = in_sizes[1] / 32;
    int E    = in_sizes[2] / 2;

    float *xa, *xm, *ya, *ym, *agg, *cnt, *gsum, *gsqs;
    cudaGetSymbolAddress((void**)&xa,   g_xa);
    cudaGetSymbolAddress((void**)&xm,   g_xm);
    cudaGetSymbolAddress((void**)&ya,   g_ya);
    cudaGetSymbolAddress((void**)&ym,   g_ym);
    cudaGetSymbolAddress((void**)&agg,  g_agg);
    cudaGetSymbolAddress((void**)&cnt,  g_cnt);
    cudaGetSymbolAddress((void**)&gsum, g_sum);
    cudaGetSymbolAddress((void**)&gsqs, g_sqs);

    int agrid = (nacc + 127) / 128;
    int mgrid = (nmer + 127) / 128;
    int eblocks = (E + 7) / 8;

    // --- input projections (tf32 mma) ---
    mma_gemm<128, 0, false><<<agrid, 256>>>(nacc, 64, x_acc, nullptr, nullptr,
                                            projW_acc, nullptr, projb_acc, xa);
    mma_gemm<128, 0, false><<<mgrid, 256>>>(nmer, 32, x_mer, nullptr, nullptr,
                                            projW_mer, nullptr, projb_mer, xm);

    int douts[3] = {128, 128, 64};
    for (int L = 0; L < 3; L++) {
        int DO = douts[L];

        // (a) pays: acc -> mer. Dead at L==2 (merchant output unused).
        if (L < 2) {
            cudaMemsetAsync(agg, 0, (size_t)nmer * 128 * sizeof(float), 0);
            cudaMemsetAsync(cnt, 0, (size_t)nmer * sizeof(float), 0);
            edge_agg_kernel<<<eblocks, 256>>>(ei_pays, E, xa, agg, cnt);
            launch_sage<128, false>(nmer, agg, xm, cnt,
                                    Wl[L] + 0 * (size_t)DO * 128,
                                    Wr[L] + 0 * (size_t)DO * 128,
                                    bl[L] + 0 * DO, ym);
        }

        // (b) rev: mer -> acc
        cudaMemsetAsync(agg, 0, (size_t)nacc * 128 * sizeof(float), 0);
        cudaMemsetAsync(cnt, 0, (size_t)nacc * sizeof(float), 0);
        edge_agg_kernel<<<eblocks, 256>>>(ei_rev, E, xm, agg, cnt);
        if (DO == 128)
            launch_sage<128, false>(nacc, agg, xa, cnt,
                                    Wl[L] + 1 * (size_t)DO * 128,
                                    Wr[L] + 1 * (size_t)DO * 128,
                                    bl[L] + 1 * DO, ya);
        else
            launch_sage<64, false>(nacc, agg, xa, cnt,
                                   Wl[L] + 1 * (size_t)DO * 128,
                                   Wr[L] + 1 * (size_t)DO * 128,
                                   bl[L] + 1 * DO, ya);

        // (c) transfer: acc -> acc (accumulate: HeteroConv sum)
        cudaMemsetAsync(agg, 0, (size_t)nacc * 128 * sizeof(float), 0);
        cudaMemsetAsync(cnt, 0, (size_t)nacc * sizeof(float), 0);
        edge_agg_kernel<<<eblocks, 256>>>(ei_tr, E, xa, agg, cnt);
        if (DO == 128)
            launch_sage<128, true>(nacc, agg, xa, cnt,
                                   Wl[L] + 2 * (size_t)DO * 128,
                                   Wr[L] + 2 * (size_t)DO * 128,
                                   bl[L] + 2 * DO, ya);
        else
            launch_sage<64, true>(nacc, agg, xa, cnt,
                                  Wl[L] + 2 * (size_t)DO * 128,
                                  Wr[L] + 2 * (size_t)DO * 128,
                                  bl[L] + 2 * DO, ya);

        // (d) BN account (+ReLU except last layer)
        cudaMemsetAsync(gsum, 0, DO * sizeof(float), 0);
        cudaMemsetAsync(gsqs, 0, DO * sizeof(float), 0);
        bn_stats_kernel<<<512, DO>>>(ya, nacc, gsum, gsqs);
        bn_apply_kernel<<<2048, 256>>>(ya, xa, nacc, DO, gsum, gsqs,
                                       bng[L] + 0 * DO, bnb[L] + 0 * DO, (L < 2) ? 1 : 0);

        // (e) BN merchant (+ReLU). Dead at L==2.
        if (L < 2) {
            cudaMemsetAsync(gsum, 0, DO * sizeof(float), 0);
            cudaMemsetAsync(gsqs, 0, DO * sizeof(float), 0);
            bn_stats_kernel<<<512, DO>>>(ym, nmer, gsum, gsqs);
            bn_apply_kernel<<<2048, 256>>>(ym, xm, nmer, DO, gsum, gsqs,
                                           bng[L] + 1 * DO, bnb[L] + 1 * DO, 1);
        }
    }

    // --- classifier head on accounts ---
    classifier_kernel<<<(nacc + 7) / 8, 256>>>(xa, nacc, clfW1, clfb1, clfW2, clfb2, out);
}

// round 4
// speedup vs baseline: 1.3811x; 1.0288x over previous
#include <cuda_runtime.h>
#include <math.h>
#include <stdint.h>

#define NACC_MAX 200000
#define NMER_MAX 100000
#define E_MAX    500000

// ---------------- scratch (device globals; no allocations allowed) -------------
__device__ float g_xa[(size_t)NACC_MAX * 128];
__device__ float g_xm[(size_t)NMER_MAX * 128];
__device__ float g_ya[(size_t)NACC_MAX * 128];
__device__ float g_ym[(size_t)NMER_MAX * 128];
__device__ float g_agg[(size_t)NACC_MAX * 128];
__device__ int   g_rowptr[3][NACC_MAX + 1];
__device__ int   g_csr[3][E_MAX];
__device__ int   g_deg[NACC_MAX];
__device__ int   g_cur[NACC_MAX];
__device__ int   g_bsum[1024];
__device__ float g_stat[4 * 128];   // [sum_a | sqs_a | sum_m | sqs_m]

// ---------------- helpers --------------------------------------------------------
__device__ __forceinline__ void split_tf32(float x, uint32_t& hi, uint32_t& lo) {
    asm("cvt.rna.tf32.f32 %0, %1;" : "=r"(hi) : "f"(x));
    float r = x - __uint_as_float(hi);
    asm("cvt.rna.tf32.f32 %0, %1;" : "=r"(lo) : "f"(r));
}

__device__ __forceinline__ void mma_tf32(float* d, const uint32_t* a,
                                         uint32_t b0, uint32_t b1) {
    asm volatile(
        "mma.sync.aligned.m16n8k8.row.col.f32.tf32.tf32.f32 "
        "{%0,%1,%2,%3}, {%4,%5,%6,%7}, {%8,%9}, {%0,%1,%2,%3};"
        : "+f"(d[0]), "+f"(d[1]), "+f"(d[2]), "+f"(d[3])
        : "r"(a[0]), "r"(a[1]), "r"(a[2]), "r"(a[3]), "r"(b0), "r"(b1));
}

__device__ __forceinline__ uint32_t saddr(const void* p) {
    uint32_t a;
    asm("{ .reg .u64 t; cvta.to.shared.u64 t, %1; cvt.u32.u64 %0, t; }"
        : "=r"(a) : "l"(p));
    return a;
}

__device__ __forceinline__ void cp16(uint32_t dst, const void* src, bool pred) {
    asm volatile("cp.async.cg.shared.global [%0], [%1], 16, %2;"
                 :: "r"(dst), "l"(src), "r"(pred ? 16 : 0) : "memory");
}
__device__ __forceinline__ void cp_commit() {
    asm volatile("cp.async.commit_group;" ::: "memory");
}

// ---------------- CSR build ------------------------------------------------------
__global__ void hist_kernel(const int* __restrict__ ei, int E, int* __restrict__ deg) {
    int e = blockIdx.x * blockDim.x + threadIdx.x;
    if (e >= E) return;
    atomicAdd(&deg[ei[E + e]], 1);
}

__global__ void scan1(const int* __restrict__ deg, int n,
                      int* __restrict__ rowptr, int* __restrict__ bsum) {
    __shared__ int s[1024];
    int i = blockIdx.x * 1024 + threadIdx.x;
    int v = (i < n) ? deg[i] : 0;
    s[threadIdx.x] = v;
    __syncthreads();
    for (int off = 1; off < 1024; off <<= 1) {
        int t = (threadIdx.x >= off) ? s[threadIdx.x - off] : 0;
        __syncthreads();
        s[threadIdx.x] += t;
        __syncthreads();
    }
    if (i < n) rowptr[i + 1] = s[threadIdx.x];
    if (threadIdx.x == 1023) bsum[blockIdx.x] = s[1023];
}

__global__ void scan2(int* __restrict__ bsum, int nb) {
    __shared__ int s[1024];
    int v = (threadIdx.x < nb) ? bsum[threadIdx.x] : 0;
    s[threadIdx.x] = v;
    __syncthreads();
    for (int off = 1; off < 1024; off <<= 1) {
        int t = (threadIdx.x >= off) ? s[threadIdx.x - off] : 0;
        __syncthreads();
        s[threadIdx.x] += t;
        __syncthreads();
    }
    if (threadIdx.x < nb) bsum[threadIdx.x] = s[threadIdx.x] - v;  // exclusive
}

__global__ void scan3(int n, int* __restrict__ rowptr, const int* __restrict__ bsum) {
    int i = blockIdx.x * blockDim.x + threadIdx.x;
    if (i < n) rowptr[i + 1] += bsum[i >> 10];
    if (i == 0) rowptr[0] = 0;
}

__global__ void scatter_kernel(const int* __restrict__ ei, int E,
                               int* __restrict__ cur, int* __restrict__ csr) {
    int e = blockIdx.x * blockDim.x + threadIdx.x;
    if (e >= E) return;
    int src = ei[e], dst = ei[E + e];
    int pos = atomicAdd(&cur[dst], 1);
    csr[pos] = src;
}

// ---------------- mean aggregation: warp per dst over CSR ----------------------
__global__ __launch_bounds__(256)
void agg_csr(const int* __restrict__ rowptr, const int* __restrict__ csr,
             const float* __restrict__ xsrc, float* __restrict__ out, int ndst)
{
    int w = (blockIdx.x * blockDim.x + threadIdx.x) >> 5;
    int lane = threadIdx.x & 31;
    if (w >= ndst) return;
    int s = __ldg(&rowptr[w]), e = __ldg(&rowptr[w + 1]);
    float4 acc = make_float4(0.f, 0.f, 0.f, 0.f);
    for (int i = s; i < e; i++) {
        int src = __ldg(&csr[i]);
        float4 v = __ldg(reinterpret_cast<const float4*>(xsrc + (size_t)src * 128) + lane);
        acc.x += v.x; acc.y += v.y; acc.z += v.z; acc.w += v.w;
    }
    float inv = 1.f / fmaxf((float)(e - s), 1.f);
    acc.x *= inv; acc.y *= inv; acc.z *= inv; acc.w *= inv;
    *(reinterpret_cast<float4*>(out + (size_t)w * 128) + lane) = acc;
}

// ---------------- split-tf32 (3x mma) pipelined GEMM -----------------------------
// D[128, DO] per CTA = A[128, K] @ B[DO, K]^T, fp32-accurate via hi/lo tf32 split.
// MODE 0: A = A1[n,K] (input projection), epilogue = +bias.
// MODE 1: K=256, A = [mean_agg | xdst], B = [Wl | Wr]; epilogue = +bias,
//         row L2-normalize, optional += into C (HeteroConv sum).
// STATS : fused BatchNorm batch statistics (column sum / sumsq) on final values.
// 512 threads = 16 warps, 4(m) x 4(n); warp tile 32m x (DO/4)n; BK=16, cp.async x2.
template<int DO, int MODE, bool ACCUM, bool STATS>
__global__ __launch_bounds__(512)
void mma_gemm(int n, int K,
              const float* __restrict__ A1, const float* __restrict__ A2,
              const float* __restrict__ B1, const float* __restrict__ B2,
              const float* __restrict__ bias, float* __restrict__ C,
              float* __restrict__ gsum, float* __restrict__ gsqs)
{
    constexpr int NJ = DO / 32;
    __shared__ float As[2][128][20];
    __shared__ float Bs[2][128][20];
    __shared__ float sBias[DO];
    __shared__ float ssRow[128];
    __shared__ float sCS[DO], sCQ[DO];

    int tid = threadIdx.x, lane = tid & 31, warp = tid >> 5;
    int g = lane >> 2, t = lane & 3;
    int wm = warp & 3, wn = warp >> 2;
    int row0 = blockIdx.x * 128;

    if (tid < DO) {
        sBias[tid] = bias[tid];
        if (STATS) { sCS[tid] = 0.f; sCQ[tid] = 0.f; }
    }
    if (tid < 128) ssRow[tid] = 0.f;

    float acc[2][NJ][4];
#pragma unroll
    for (int i = 0; i < 2; i++)
#pragma unroll
        for (int j = 0; j < NJ; j++)
#pragma unroll
            for (int c = 0; c < 4; c++) acc[i][j][c] = 0.f;

    const int T = K >> 4;

    auto load_tile = [&](int kt, int buf) {
        {   // A tile 128x16: 1 float4 per thread
            int m = tid >> 2, q = tid & 3, k = kt * 16 + q * 4;
            int r = row0 + m;
            bool p = (r < n);
            int rc = p ? r : 0;
            const float* src;
            if (MODE == 0) src = A1 + (size_t)rc * K + k;
            else src = (k < 128) ? A1 + (size_t)rc * 128 + k
                                 : A2 + (size_t)rc * 128 + (k - 128);
            cp16(saddr(&As[buf][m][q * 4]), src, p);
        }
        if (tid < DO * 4) {  // B tile DOx16
            int j = tid >> 2, q = tid & 3, k = kt * 16 + q * 4;
            const float* src;
            if (MODE == 1) src = (k < 128) ? B1 + (size_t)j * 128 + k
                                           : B2 + (size_t)j * 128 + (k - 128);
            else src = B1 + (size_t)j * K + k;
            cp16(saddr(&Bs[buf][j][q * 4]), src, true);
        }
    };

    auto compute = [&](int buf) {
#pragma unroll
        for (int ks = 0; ks < 16; ks += 8) {
            uint32_t ah[2][4], al[2][4];
#pragma unroll
            for (int i = 0; i < 2; i++) {
                int rb = wm * 32 + i * 16;
                split_tf32(As[buf][rb + g][ks + t],     ah[i][0], al[i][0]);
                split_tf32(As[buf][rb + g + 8][ks + t], ah[i][1], al[i][1]);
                split_tf32(As[buf][rb + g][ks + t + 4],     ah[i][2], al[i][2]);
                split_tf32(As[buf][rb + g + 8][ks + t + 4], ah[i][3], al[i][3]);
            }
#pragma unroll
            for (int j = 0; j < NJ; j++) {
                int nb = wn * (NJ * 8) + j * 8 + g;
                uint32_t bh0, bl0, bh1, bl1;
                split_tf32(Bs[buf][nb][ks + t],     bh0, bl0);
                split_tf32(Bs[buf][nb][ks + t + 4], bh1, bl1);
#pragma unroll
                for (int i = 0; i < 2; i++) {
                    mma_tf32(acc[i][j], al[i], bh0, bh1);
                    mma_tf32(acc[i][j], ah[i], bl0, bl1);
                    mma_tf32(acc[i][j], ah[i], bh0, bh1);
                }
            }
        }
    };

    load_tile(0, 0);
    cp_commit();
    for (int kt = 0; kt < T; kt++) {
        if (kt + 1 < T) { load_tile(kt + 1, (kt + 1) & 1); cp_commit(); }
        if (kt + 1 < T) asm volatile("cp.async.wait_group 1;" ::: "memory");
        else            asm volatile("cp.async.wait_group 0;" ::: "memory");
        __syncthreads();
        compute(kt & 1);
        __syncthreads();
    }

    // ---- epilogue: bias, row L2-norm, accumulate, fused BN stats ----
#pragma unroll
    for (int i = 0; i < 2; i++) {
        float ss0 = 0.f, ss1 = 0.f;
#pragma unroll
        for (int j = 0; j < NJ; j++) {
            int cb = wn * (NJ * 8) + j * 8 + t * 2;
            float b0 = sBias[cb], b1 = sBias[cb + 1];
            acc[i][j][0] += b0; acc[i][j][1] += b1;
            acc[i][j][2] += b0; acc[i][j][3] += b1;
            if (MODE == 1) {
                ss0 += acc[i][j][0] * acc[i][j][0] + acc[i][j][1] * acc[i][j][1];
                ss1 += acc[i][j][2] * acc[i][j][2] + acc[i][j][3] * acc[i][j][3];
            }
        }
        if (MODE == 1) {
            ss0 += __shfl_xor_sync(0xffffffffu, ss0, 1);
            ss0 += __shfl_xor_sync(0xffffffffu, ss0, 2);
            ss1 += __shfl_xor_sync(0xffffffffu, ss1, 1);
            ss1 += __shfl_xor_sync(0xffffffffu, ss1, 2);
            if (t == 0) {
                atomicAdd(&ssRow[wm * 32 + i * 16 + g], ss0);
                atomicAdd(&ssRow[wm * 32 + i * 16 + g + 8], ss1);
            }
        }
    }
    __syncthreads();

    float cs[NJ][2], cq[NJ][2];
    if (STATS) {
#pragma unroll
        for (int j = 0; j < NJ; j++) { cs[j][0] = cs[j][1] = cq[j][0] = cq[j][1] = 0.f; }
    }

#pragma unroll
    for (int i = 0; i < 2; i++) {
        int rl = wm * 32 + i * 16 + g;
        float s0 = 1.f, s1 = 1.f;
        if (MODE == 1) {
            s0 = 1.f / fmaxf(sqrtf(ssRow[rl]), 1e-12f);
            s1 = 1.f / fmaxf(sqrtf(ssRow[rl + 8]), 1e-12f);
        }
        int r0 = row0 + rl, r1 = r0 + 8;
#pragma unroll
        for (int j = 0; j < NJ; j++) {
            int cb = wn * (NJ * 8) + j * 8 + t * 2;
            if (r0 < n) {
                float2* p = reinterpret_cast<float2*>(C + (size_t)r0 * DO + cb);
                float2 v = make_float2(acc[i][j][0] * s0, acc[i][j][1] * s0);
                if (ACCUM) { float2 o = *p; v.x += o.x; v.y += o.y; }
                *p = v;
                if (STATS) {
                    cs[j][0] += v.x; cs[j][1] += v.y;
                    cq[j][0] += v.x * v.x; cq[j][1] += v.y * v.y;
                }
            }
            if (r1 < n) {
                float2* p = reinterpret_cast<float2*>(C + (size_t)r1 * DO + cb);
                float2 v = make_float2(acc[i][j][2] * s1, acc[i][j][3] * s1);
                if (ACCUM) { float2 o = *p; v.x += o.x; v.y += o.y; }
                *p = v;
                if (STATS) {
                    cs[j][0] += v.x; cs[j][1] += v.y;
                    cq[j][0] += v.x * v.x; cq[j][1] += v.y * v.y;
                }
            }
        }
    }

    if (STATS) {
#pragma unroll
        for (int j = 0; j < NJ; j++)
#pragma unroll
            for (int c = 0; c < 2; c++) {
                float s = cs[j][c], q = cq[j][c];
                s += __shfl_xor_sync(0xffffffffu, s, 4);
                s += __shfl_xor_sync(0xffffffffu, s, 8);
                s += __shfl_xor_sync(0xffffffffu, s, 16);
                q += __shfl_xor_sync(0xffffffffu, q, 4);
                q += __shfl_xor_sync(0xffffffffu, q, 8);
                q += __shfl_xor_sync(0xffffffffu, q, 16);
                if (g == 0) {
                    int cb = wn * (NJ * 8) + j * 8 + t * 2 + c;
                    atomicAdd(&sCS[cb], s);
                    atomicAdd(&sCQ[cb], q);
                }
            }
        __syncthreads();
        if (tid < DO) {
            atomicAdd(&gsum[tid], sCS[tid]);
            atomicAdd(&gsqs[tid], sCQ[tid]);
        }
    }
}

// ---------------- BatchNorm apply (stats precomputed) ---------------------------
__global__ void bn_apply_kernel(const float* __restrict__ X, float* __restrict__ Y,
                                int n, int d,
                                const float* __restrict__ sum, const float* __restrict__ sqs,
                                const float* __restrict__ g, const float* __restrict__ b,
                                int relu)
{
    int d4 = d >> 2;
    size_t total = (size_t)n * d4;
    float invn = 1.f / (float)n;
    for (size_t i = blockIdx.x * (size_t)blockDim.x + threadIdx.x; i < total;
         i += (size_t)gridDim.x * blockDim.x) {
        int c = (int)(i % d4) * 4;
        float4 x = *(reinterpret_cast<const float4*>(X) + i);
        float4 y;
#pragma unroll
        for (int k = 0; k < 4; k++) {
            float mu = sum[c + k] * invn;
            float var = sqs[c + k] * invn - mu * mu;
            float xv = (&x.x)[k];
            float yv = (xv - mu) * rsqrtf(var + 1e-5f) * g[c + k] + b[c + k];
            if (relu) yv = fmaxf(yv, 0.f);
            (&y.x)[k] = yv;
        }
        *(reinterpret_cast<float4*>(Y) + i) = y;
    }
}

// ---------------- fused classifier: relu(x@W1^T+b1)@W2^T+b2 --------------------
__global__ __launch_bounds__(256)
void classifier_kernel(const float* __restrict__ X, int n,
                       const float* __restrict__ W1, const float* __restrict__ b1,
                       const float* __restrict__ W2, const float* __restrict__ b2,
                       float* __restrict__ out)
{
    __shared__ float sW1[64 * 65];
    __shared__ float sW2[64];
    __shared__ float sb1[64];
    int tid = threadIdx.x;
    for (int i = tid; i < 64 * 64; i += 256) {
        int j = i >> 6, k = i & 63;
        sW1[j * 65 + k] = W1[i];
    }
    if (tid < 64) { sW2[tid] = W2[tid]; sb1[tid] = b1[tid]; }
    __syncthreads();

    int lane = tid & 31;
    int row = blockIdx.x * 8 + (tid >> 5);
    if (row >= n) return;
    float x0 = X[(size_t)row * 64 + lane];
    float x1 = X[(size_t)row * 64 + 32 + lane];
    float h0 = sb1[lane], h1 = sb1[lane + 32];
#pragma unroll
    for (int k = 0; k < 32; k++) {
        float xk = __shfl_sync(0xffffffffu, x0, k);
        h0 += xk * sW1[lane * 65 + k];
        h1 += xk * sW1[(lane + 32) * 65 + k];
    }
#pragma unroll
    for (int k = 0; k < 32; k++) {
        float xk = __shfl_sync(0xffffffffu, x1, k);
        h0 += xk * sW1[lane * 65 + 32 + k];
        h1 += xk * sW1[(lane + 32) * 65 + 32 + k];
    }
    h0 = fmaxf(h0, 0.f); h1 = fmaxf(h1, 0.f);
    float p = h0 * sW2[lane] + h1 * sW2[lane + 32];
#pragma unroll
    for (int off = 16; off; off >>= 1)
        p += __shfl_xor_sync(0xffffffffu, p, off);
    if (lane == 0) out[row] = p + b2[0];
}

// ---------------- host-side CSR build --------------------------------------------
static void build_csr(const int* ei, int E, int ndst,
                      int* rowptr, int* csr, int* deg, int* cur, int* bsum)
{
    cudaMemsetAsync(deg, 0, (size_t)ndst * sizeof(int), 0);
    hist_kernel<<<(E + 255) / 256, 256>>>(ei, E, deg);
    int nb = (ndst + 1023) / 1024;
    scan1<<<nb, 1024>>>(deg, ndst, rowptr, bsum);
    scan2<<<1, 1024>>>(bsum, nb);
    scan3<<<(ndst + 255) / 256, 256>>>(ndst, rowptr, bsum);
    cudaMemcpyAsync(cur, rowptr, (size_t)ndst * sizeof(int),
                    cudaMemcpyDeviceToDevice, 0);
    scatter_kernel<<<(E + 255) / 256, 256>>>(ei, E, cur, csr);
}

// ---------------- kernel_launch -------------------------------------------------
extern "C" void kernel_launch(void* const* d_in, const int* in_sizes, int n_in,
                              void* d_out, int out_size)
{
    const float* x_acc      = (const float*)d_in[0];
    const float* x_mer      = (const float*)d_in[1];
    const int*   ei_pays    = (const int*)d_in[2];
    const int*   ei_rev     = (const int*)d_in[3];
    const int*   ei_tr      = (const int*)d_in[4];
    const float* projW_acc  = (const float*)d_in[5];
    const float* projb_acc  = (const float*)d_in[6];
    const float* projW_mer  = (const float*)d_in[7];
    const float* projb_mer  = (const float*)d_in[8];
    const float* Wl[3] = {(const float*)d_in[9],  (const float*)d_in[12], (const float*)d_in[15]};
    const float* bl[3] = {(const float*)d_in[10], (const float*)d_in[13], (const float*)d_in[16]};
    const float* Wr[3] = {(const float*)d_in[11], (const float*)d_in[14], (const float*)d_in[17]};
    const float* bng[3] = {(const float*)d_in[18], (const float*)d_in[20], (const float*)d_in[22]};
    const float* bnb[3] = {(const float*)d_in[19], (const float*)d_in[21], (const float*)d_in[23]};
    const float* clfW1 = (const float*)d_in[24];
    const float* clfb1 = (const float*)d_in[25];
    const float* clfW2 = (const float*)d_in[26];
    const float* clfb2 = (const float*)d_in[27];
    float* out = (float*)d_out;

    int nacc = in_sizes[0] / 64;
    int nmer = in_sizes[1] / 32;
    int E    = in_sizes[2] / 2;

    float *xa, *xm, *ya, *ym, *agg, *stat;
    int *rowptr, *csr, *deg, *cur, *bsum;
    cudaGetSymbolAddress((void**)&xa,     g_xa);
    cudaGetSymbolAddress((void**)&xm,     g_xm);
    cudaGetSymbolAddress((void**)&ya,     g_ya);
    cudaGetSymbolAddress((void**)&ym,     g_ym);
    cudaGetSymbolAddress((void**)&agg,    g_agg);
    cudaGetSymbolAddress((void**)&stat,   g_stat);
    cudaGetSymbolAddress((void**)&rowptr, g_rowptr);
    cudaGetSymbolAddress((void**)&csr,    g_csr);
    cudaGetSymbolAddress((void**)&deg,    g_deg);
    cudaGetSymbolAddress((void**)&cur,    g_cur);
    cudaGetSymbolAddress((void**)&bsum,   g_bsum);

    int* rp[3]  = {rowptr, rowptr + (NACC_MAX + 1), rowptr + 2 * (NACC_MAX + 1)};
    int* cs3[3] = {csr, csr + E_MAX, csr + 2 * E_MAX};
    float* sum_a = stat;        float* sqs_a = stat + 128;
    float* sum_m = stat + 256;  float* sqs_m = stat + 384;

    // --- CSR builds (one per edge type, reused across layers) ---
    build_csr(ei_pays, E, nmer, rp[0], cs3[0], deg, cur, bsum);
    build_csr(ei_rev,  E, nacc, rp[1], cs3[1], deg, cur, bsum);
    build_csr(ei_tr,   E, nacc, rp[2], cs3[2], deg, cur, bsum);

    int agrid = (nacc + 127) / 128;
    int mgrid = (nmer + 127) / 128;
    int awgrid = (nacc * 32 + 255) / 256;
    int mwgrid = (nmer * 32 + 255) / 256;

    // --- input projections ---
    mma_gemm<128, 0, false, false><<<agrid, 512>>>(nacc, 64, x_acc, nullptr,
        projW_acc, nullptr, projb_acc, xa, nullptr, nullptr);
    mma_gemm<128, 0, false, false><<<mgrid, 512>>>(nmer, 32, x_mer, nullptr,
        projW_mer, nullptr, projb_mer, xm, nullptr, nullptr);

    int douts[3] = {128, 128, 64};
    for (int L = 0; L < 3; L++) {
        int DO = douts[L];

        // (a) pays: acc -> mer (dead at L==2); emits merchant BN stats
        if (L < 2) {
            agg_csr<<<mwgrid, 256>>>(rp[0], cs3[0], xa, agg, nmer);
            cudaMemsetAsync(sum_m, 0, 256 * sizeof(float), 0);
            mma_gemm<128, 1, false, true><<<mgrid, 512>>>(nmer, 256, agg, xm,
                Wl[L] + 0 * (size_t)DO * 128, Wr[L] + 0 * (size_t)DO * 128,
                bl[L] + 0 * DO, ym, sum_m, sqs_m);
        }

        // (b) rev: mer -> acc (no stats: not final value yet)
        agg_csr<<<awgrid, 256>>>(rp[1], cs3[1], xm, agg, nacc);
        if (DO == 128)
            mma_gemm<128, 1, false, false><<<agrid, 512>>>(nacc, 256, agg, xa,
                Wl[L] + 1 * (size_t)DO * 128, Wr[L] + 1 * (size_t)DO * 128,
                bl[L] + 1 * DO, ya, nullptr, nullptr);
        else
            mma_gemm<64, 1, false, false><<<agrid, 512>>>(nacc, 256, agg, xa,
                Wl[L] + 1 * (size_t)DO * 128, Wr[L] + 1 * (size_t)DO * 128,
                bl[L] + 1 * DO, ya, nullptr, nullptr);

        // (c) transfer: acc -> acc (HeteroConv +=); emits account BN stats
        agg_csr<<<awgrid, 256>>>(rp[2], cs3[2], xa, agg, nacc);
        cudaMemsetAsync(sum_a, 0, 256 * sizeof(float), 0);
        if (DO == 128)
            mma_gemm<128, 1, true, true><<<agrid, 512>>>(nacc, 256, agg, xa,
                Wl[L] + 2 * (size_t)DO * 128, Wr[L] + 2 * (size_t)DO * 128,
                bl[L] + 2 * DO, ya, sum_a, sqs_a);
        else
            mma_gemm<64, 1, true, true><<<agrid, 512>>>(nacc, 256, agg, xa,
                Wl[L] + 2 * (size_t)DO * 128, Wr[L] + 2 * (size_t)DO * 128,
                bl[L] + 2 * DO, ya, sum_a, sqs_a);

        // (d) BN account (+ReLU except last layer)
        bn_apply_kernel<<<2048, 256>>>(ya, xa, nacc, DO, sum_a, sqs_a,
                                       bng[L] + 0 * DO, bnb[L] + 0 * DO, (L < 2) ? 1 : 0);

        // (e) BN merchant (+ReLU); dead at L==2
        if (L < 2) {
            bn_apply_kernel<<<2048, 256>>>(ym, xm, nmer, DO, sum_m, sqs_m,
                                           bng[L] + 1 * DO, bnb[L] + 1 * DO, 1);
        }
    }

    // --- classifier head on accounts ---
    classifier_kernel<<<(nacc + 7) / 8, 256>>>(xa, nacc, clfW1, clfb1, clfW2, clfb2, out);
}

// round 5
// speedup vs baseline: 1.6597x; 1.2018x over previous
#include <cuda_runtime.h>
#include <math.h>
#include <stdint.h>

#define NACC_MAX 200000
#define NMER_MAX 100000
#define E_MAX    500000

// ---------------- scratch (device globals; no allocations allowed) -------------
__device__ float g_xa[(size_t)NACC_MAX * 128];
__device__ float g_xm[(size_t)NMER_MAX * 128];
__device__ float g_ya[(size_t)NACC_MAX * 128];
__device__ float g_ym[(size_t)NMER_MAX * 128];
__device__ float g_agg[(size_t)NACC_MAX * 128];   // rev -> acc
__device__ float g_agg2[(size_t)NACC_MAX * 128];  // transfer -> acc
__device__ float g_aggm[(size_t)NMER_MAX * 128];  // pays -> mer
__device__ int   g_rowptr[3][NACC_MAX + 1];
__device__ int   g_csr[3][E_MAX];
__device__ int   g_deg[NACC_MAX];
__device__ int   g_cur[NACC_MAX];
__device__ int   g_bsum[1024];
__device__ float g_stat[4 * 128];   // [sum_a | sqs_a | sum_m | sqs_m]

// ---------------- bf16x3 emulation helpers ---------------------------------------
// Split a float2 (adjacent k) into packed bf16x2 hi (truncated) + lo (residual).
__device__ __forceinline__ void split2(float2 v, uint32_t& h, uint32_t& l) {
    uint32_t u0 = __float_as_uint(v.x), u1 = __float_as_uint(v.y);
    h = __byte_perm(u0, u1, 0x7632);                    // {hi16(v1), hi16(v0)}
    float r0 = v.x - __uint_as_float(u0 & 0xFFFF0000u); // exact residual
    float r1 = v.y - __uint_as_float(u1 & 0xFFFF0000u);
    asm("cvt.rn.bf16x2.f32 %0, %1, %2;" : "=r"(l) : "f"(r1), "f"(r0));
}

__device__ __forceinline__ void mma_bf16(float* d, const uint32_t* a,
                                         uint32_t b0, uint32_t b1) {
    asm volatile(
        "mma.sync.aligned.m16n8k16.row.col.f32.bf16.bf16.f32 "
        "{%0,%1,%2,%3}, {%4,%5,%6,%7}, {%8,%9}, {%0,%1,%2,%3};"
        : "+f"(d[0]), "+f"(d[1]), "+f"(d[2]), "+f"(d[3])
        : "r"(a[0]), "r"(a[1]), "r"(a[2]), "r"(a[3]), "r"(b0), "r"(b1));
}

__device__ __forceinline__ uint32_t saddr(const void* p) {
    uint32_t a;
    asm("{ .reg .u64 t; cvta.to.shared.u64 t, %1; cvt.u32.u64 %0, t; }"
        : "=r"(a) : "l"(p));
    return a;
}

__device__ __forceinline__ void cp16(uint32_t dst, const void* src, bool pred) {
    asm volatile("cp.async.cg.shared.global [%0], [%1], 16, %2;"
                 :: "r"(dst), "l"(src), "r"(pred ? 16 : 0) : "memory");
}
__device__ __forceinline__ void cp_commit() {
    asm volatile("cp.async.commit_group;" ::: "memory");
}

// ---------------- CSR build ------------------------------------------------------
__global__ void hist_kernel(const int* __restrict__ ei, int E, int* __restrict__ deg) {
    int e = blockIdx.x * blockDim.x + threadIdx.x;
    if (e >= E) return;
    atomicAdd(&deg[ei[E + e]], 1);
}

__global__ void scan1(const int* __restrict__ deg, int n,
                      int* __restrict__ rowptr, int* __restrict__ bsum) {
    __shared__ int s[1024];
    int i = blockIdx.x * 1024 + threadIdx.x;
    int v = (i < n) ? deg[i] : 0;
    s[threadIdx.x] = v;
    __syncthreads();
    for (int off = 1; off < 1024; off <<= 1) {
        int t = (threadIdx.x >= off) ? s[threadIdx.x - off] : 0;
        __syncthreads();
        s[threadIdx.x] += t;
        __syncthreads();
    }
    if (i < n) rowptr[i + 1] = s[threadIdx.x];
    if (threadIdx.x == 1023) bsum[blockIdx.x] = s[1023];
}

__global__ void scan2(int* __restrict__ bsum, int nb) {
    __shared__ int s[1024];
    int v = (threadIdx.x < nb) ? bsum[threadIdx.x] : 0;
    s[threadIdx.x] = v;
    __syncthreads();
    for (int off = 1; off < 1024; off <<= 1) {
        int t = (threadIdx.x >= off) ? s[threadIdx.x - off] : 0;
        __syncthreads();
        s[threadIdx.x] += t;
        __syncthreads();
    }
    if (threadIdx.x < nb) bsum[threadIdx.x] = s[threadIdx.x] - v;  // exclusive
}

__global__ void scan3(int n, int* __restrict__ rowptr, const int* __restrict__ bsum) {
    int i = blockIdx.x * blockDim.x + threadIdx.x;
    if (i < n) rowptr[i + 1] += bsum[i >> 10];
    if (i == 0) rowptr[0] = 0;
}

__global__ void scatter_kernel(const int* __restrict__ ei, int E,
                               int* __restrict__ cur, int* __restrict__ csr) {
    int e = blockIdx.x * blockDim.x + threadIdx.x;
    if (e >= E) return;
    int src = ei[e], dst = ei[E + e];
    int pos = atomicAdd(&cur[dst], 1);
    csr[pos] = src;
}

// ---------------- fused mean aggregation: all edge types, warp per dst ----------
__global__ __launch_bounds__(256)
void agg_all(int n0, const int* __restrict__ rp0, const int* __restrict__ cs0,
             const float* __restrict__ src0, float* __restrict__ out0,
             int n1, const int* __restrict__ rp1, const int* __restrict__ cs1,
             const float* __restrict__ src1, float* __restrict__ out1,
             int n2, const int* __restrict__ rp2, const int* __restrict__ cs2,
             const float* __restrict__ src2, float* __restrict__ out2)
{
    int w = (blockIdx.x * blockDim.x + threadIdx.x) >> 5;
    int lane = threadIdx.x & 31;
    const int *rp, *cs; const float* src; float* out; int d;
    if (w < n0)           { rp = rp0; cs = cs0; src = src0; out = out0; d = w; }
    else if (w < n0 + n1) { rp = rp1; cs = cs1; src = src1; out = out1; d = w - n0; }
    else if (w < n0 + n1 + n2) { rp = rp2; cs = cs2; src = src2; out = out2; d = w - n0 - n1; }
    else return;

    int s = __ldg(&rp[d]), e = __ldg(&rp[d + 1]);
    float4 acc = make_float4(0.f, 0.f, 0.f, 0.f);
    int i = s;
    for (; i + 2 <= e; i += 2) {
        int s0 = __ldg(&cs[i]), s1 = __ldg(&cs[i + 1]);
        float4 v0 = __ldg(reinterpret_cast<const float4*>(src + (size_t)s0 * 128) + lane);
        float4 v1 = __ldg(reinterpret_cast<const float4*>(src + (size_t)s1 * 128) + lane);
        acc.x += v0.x + v1.x; acc.y += v0.y + v1.y;
        acc.z += v0.z + v1.z; acc.w += v0.w + v1.w;
    }
    if (i < e) {
        int s0 = __ldg(&cs[i]);
        float4 v0 = __ldg(reinterpret_cast<const float4*>(src + (size_t)s0 * 128) + lane);
        acc.x += v0.x; acc.y += v0.y; acc.z += v0.z; acc.w += v0.w;
    }
    float inv = 1.f / fmaxf((float)(e - s), 1.f);
    acc.x *= inv; acc.y *= inv; acc.z *= inv; acc.w *= inv;
    *(reinterpret_cast<float4*>(out + (size_t)d * 128) + lane) = acc;
}

// ---------------- bf16x3 (3x mma.m16n8k16) pipelined GEMM ------------------------
// D[128, DO] per CTA = A[128, K] @ B[DO, K]^T, fp32-accurate via hi/lo bf16 split:
//   d += ah*bh + ah*bl + al*bh   (dropped al*bl + residual ~ 2^-15/elem)
// MODE 0: A = A1[n,K] (input projection), epilogue = +bias.
// MODE 1: K=256, A = [mean_agg | xdst], B = [Wl | Wr]; epilogue = +bias,
//         row L2-normalize, optional += into C (HeteroConv sum).
// STATS : fused BatchNorm batch statistics (column sum / sumsq) on final values.
// 512 threads = 16 warps, 4(m) x 4(n); warp tile 32m x (DO/4)n; BK=16, cp.async x2.
template<int DO, int MODE, bool ACCUM, bool STATS>
__global__ __launch_bounds__(512)
void mma_gemm(int n, int K,
              const float* __restrict__ A1, const float* __restrict__ A2,
              const float* __restrict__ B1, const float* __restrict__ B2,
              const float* __restrict__ bias, float* __restrict__ C,
              float* __restrict__ gsum, float* __restrict__ gsqs)
{
    constexpr int NJ = DO / 32;
    __shared__ float As[2][128][20];
    __shared__ float Bs[2][128][20];
    __shared__ float sBias[DO];
    __shared__ float ssRow[128];
    __shared__ float sCS[DO], sCQ[DO];

    int tid = threadIdx.x, lane = tid & 31, warp = tid >> 5;
    int g = lane >> 2, t = lane & 3;
    int wm = warp & 3, wn = warp >> 2;
    int row0 = blockIdx.x * 128;

    if (tid < DO) {
        sBias[tid] = bias[tid];
        if (STATS) { sCS[tid] = 0.f; sCQ[tid] = 0.f; }
    }
    if (tid < 128) ssRow[tid] = 0.f;

    float acc[2][NJ][4];
#pragma unroll
    for (int i = 0; i < 2; i++)
#pragma unroll
        for (int j = 0; j < NJ; j++)
#pragma unroll
            for (int c = 0; c < 4; c++) acc[i][j][c] = 0.f;

    const int T = K >> 4;

    auto load_tile = [&](int kt, int buf) {
        {   // A tile 128x16: 1 float4 per thread
            int m = tid >> 2, q = tid & 3, k = kt * 16 + q * 4;
            int r = row0 + m;
            bool p = (r < n);
            int rc = p ? r : 0;
            const float* src;
            if (MODE == 0) src = A1 + (size_t)rc * K + k;
            else src = (k < 128) ? A1 + (size_t)rc * 128 + k
                                 : A2 + (size_t)rc * 128 + (k - 128);
            cp16(saddr(&As[buf][m][q * 4]), src, p);
        }
        if (tid < DO * 4) {  // B tile DOx16
            int j = tid >> 2, q = tid & 3, k = kt * 16 + q * 4;
            const float* src;
            if (MODE == 1) src = (k < 128) ? B1 + (size_t)j * 128 + k
                                           : B2 + (size_t)j * 128 + (k - 128);
            else src = B1 + (size_t)j * K + k;
            cp16(saddr(&Bs[buf][j][q * 4]), src, true);
        }
    };

    auto compute = [&](int buf) {
        uint32_t ah[2][4], al[2][4];
#pragma unroll
        for (int i = 0; i < 2; i++) {
            int rb = wm * 32 + i * 16;
            float2 v0 = *reinterpret_cast<const float2*>(&As[buf][rb + g][2 * t]);
            float2 v1 = *reinterpret_cast<const float2*>(&As[buf][rb + g + 8][2 * t]);
            float2 v2 = *reinterpret_cast<const float2*>(&As[buf][rb + g][2 * t + 8]);
            float2 v3 = *reinterpret_cast<const float2*>(&As[buf][rb + g + 8][2 * t + 8]);
            split2(v0, ah[i][0], al[i][0]);
            split2(v1, ah[i][1], al[i][1]);
            split2(v2, ah[i][2], al[i][2]);
            split2(v3, ah[i][3], al[i][3]);
        }
#pragma unroll
        for (int j = 0; j < NJ; j++) {
            int nb = wn * (NJ * 8) + j * 8 + g;
            float2 w0 = *reinterpret_cast<const float2*>(&Bs[buf][nb][2 * t]);
            float2 w1 = *reinterpret_cast<const float2*>(&Bs[buf][nb][2 * t + 8]);
            uint32_t bh0, bl0, bh1, bl1;
            split2(w0, bh0, bl0);
            split2(w1, bh1, bl1);
#pragma unroll
            for (int i = 0; i < 2; i++) {
                uint32_t bh[2] = {bh0, bh1}, bl[2] = {bl0, bl1};
                mma_bf16(acc[i][j], ah[i], bh[0], bh[1]);
                mma_bf16(acc[i][j], ah[i], bl[0], bl[1]);
                mma_bf16(acc[i][j], al[i], bh[0], bh[1]);
            }
        }
    };

    load_tile(0, 0);
    cp_commit();
    for (int kt = 0; kt < T; kt++) {
        if (kt + 1 < T) { load_tile(kt + 1, (kt + 1) & 1); cp_commit(); }
        if (kt + 1 < T) asm volatile("cp.async.wait_group 1;" ::: "memory");
        else            asm volatile("cp.async.wait_group 0;" ::: "memory");
        __syncthreads();
        compute(kt & 1);
        __syncthreads();
    }

    // ---- epilogue: bias, row L2-norm, accumulate, fused BN stats ----
#pragma unroll
    for (int i = 0; i < 2; i++) {
        float ss0 = 0.f, ss1 = 0.f;
#pragma unroll
        for (int j = 0; j < NJ; j++) {
            int cb = wn * (NJ * 8) + j * 8 + t * 2;
            float b0 = sBias[cb], b1 = sBias[cb + 1];
            acc[i][j][0] += b0; acc[i][j][1] += b1;
            acc[i][j][2] += b0; acc[i][j][3] += b1;
            if (MODE == 1) {
                ss0 += acc[i][j][0] * acc[i][j][0] + acc[i][j][1] * acc[i][j][1];
                ss1 += acc[i][j][2] * acc[i][j][2] + acc[i][j][3] * acc[i][j][3];
            }
        }
        if (MODE == 1) {
            ss0 += __shfl_xor_sync(0xffffffffu, ss0, 1);
            ss0 += __shfl_xor_sync(0xffffffffu, ss0, 2);
            ss1 += __shfl_xor_sync(0xffffffffu, ss1, 1);
            ss1 += __shfl_xor_sync(0xffffffffu, ss1, 2);
            if (t == 0) {
                atomicAdd(&ssRow[wm * 32 + i * 16 + g], ss0);
                atomicAdd(&ssRow[wm * 32 + i * 16 + g + 8], ss1);
            }
        }
    }
    __syncthreads();

    float cs[NJ][2], cq[NJ][2];
    if (STATS) {
#pragma unroll
        for (int j = 0; j < NJ; j++) { cs[j][0] = cs[j][1] = cq[j][0] = cq[j][1] = 0.f; }
    }

#pragma unroll
    for (int i = 0; i < 2; i++) {
        int rl = wm * 32 + i * 16 + g;
        float s0 = 1.f, s1 = 1.f;
        if (MODE == 1) {
            s0 = 1.f / fmaxf(sqrtf(ssRow[rl]), 1e-12f);
            s1 = 1.f / fmaxf(sqrtf(ssRow[rl + 8]), 1e-12f);
        }
        int r0 = row0 + rl, r1 = r0 + 8;
#pragma unroll
        for (int j = 0; j < NJ; j++) {
            int cb = wn * (NJ * 8) + j * 8 + t * 2;
            if (r0 < n) {
                float2* p = reinterpret_cast<float2*>(C + (size_t)r0 * DO + cb);
                float2 v = make_float2(acc[i][j][0] * s0, acc[i][j][1] * s0);
                if (ACCUM) { float2 o = *p; v.x += o.x; v.y += o.y; }
                *p = v;
                if (STATS) {
                    cs[j][0] += v.x; cs[j][1] += v.y;
                    cq[j][0] += v.x * v.x; cq[j][1] += v.y * v.y;
                }
            }
            if (r1 < n) {
                float2* p = reinterpret_cast<float2*>(C + (size_t)r1 * DO + cb);
                float2 v = make_float2(acc[i][j][2] * s1, acc[i][j][3] * s1);
                if (ACCUM) { float2 o = *p; v.x += o.x; v.y += o.y; }
                *p = v;
                if (STATS) {
                    cs[j][0] += v.x; cs[j][1] += v.y;
                    cq[j][0] += v.x * v.x; cq[j][1] += v.y * v.y;
                }
            }
        }
    }

    if (STATS) {
#pragma unroll
        for (int j = 0; j < NJ; j++)
#pragma unroll
            for (int c = 0; c < 2; c++) {
                float s = cs[j][c], q = cq[j][c];
                s += __shfl_xor_sync(0xffffffffu, s, 4);
                s += __shfl_xor_sync(0xffffffffu, s, 8);
                s += __shfl_xor_sync(0xffffffffu, s, 16);
                q += __shfl_xor_sync(0xffffffffu, q, 4);
                q += __shfl_xor_sync(0xffffffffu, q, 8);
                q += __shfl_xor_sync(0xffffffffu, q, 16);
                if (g == 0) {
                    int cb = wn * (NJ * 8) + j * 8 + t * 2 + c;
                    atomicAdd(&sCS[cb], s);
                    atomicAdd(&sCQ[cb], q);
                }
            }
        __syncthreads();
        if (tid < DO) {
            atomicAdd(&gsum[tid], sCS[tid]);
            atomicAdd(&gsqs[tid], sCQ[tid]);
        }
    }
}

// ---------------- BatchNorm apply (stats precomputed) ---------------------------
__global__ void bn_apply_kernel(const float* __restrict__ X, float* __restrict__ Y,
                                int n, int d,
                                const float* __restrict__ sum, const float* __restrict__ sqs,
                                const float* __restrict__ g, const float* __restrict__ b,
                                int relu)
{
    int d4 = d >> 2;
    size_t total = (size_t)n * d4;
    float invn = 1.f / (float)n;
    for (size_t i = blockIdx.x * (size_t)blockDim.x + threadIdx.x; i < total;
         i += (size_t)gridDim.x * blockDim.x) {
        int c = (int)(i % d4) * 4;
        float4 x = *(reinterpret_cast<const float4*>(X) + i);
        float4 y;
#pragma unroll
        for (int k = 0; k < 4; k++) {
            float mu = sum[c + k] * invn;
            float var = sqs[c + k] * invn - mu * mu;
            float xv = (&x.x)[k];
            float yv = (xv - mu) * rsqrtf(var + 1e-5f) * g[c + k] + b[c + k];
            if (relu) yv = fmaxf(yv, 0.f);
            (&y.x)[k] = yv;
        }
        *(reinterpret_cast<float4*>(Y) + i) = y;
    }
}

// ---------------- fused classifier: relu(x@W1^T+b1)@W2^T+b2 --------------------
__global__ __launch_bounds__(256)
void classifier_kernel(const float* __restrict__ X, int n,
                       const float* __restrict__ W1, const float* __restrict__ b1,
                       const float* __restrict__ W2, const float* __restrict__ b2,
                       float* __restrict__ out)
{
    __shared__ float sW1[64 * 65];
    __shared__ float sW2[64];
    __shared__ float sb1[64];
    int tid = threadIdx.x;
    for (int i = tid; i < 64 * 64; i += 256) {
        int j = i >> 6, k = i & 63;
        sW1[j * 65 + k] = W1[i];
    }
    if (tid < 64) { sW2[tid] = W2[tid]; sb1[tid] = b1[tid]; }
    __syncthreads();

    int lane = tid & 31;
    int row = blockIdx.x * 8 + (tid >> 5);
    if (row >= n) return;
    float x0 = X[(size_t)row * 64 + lane];
    float x1 = X[(size_t)row * 64 + 32 + lane];
    float h0 = sb1[lane], h1 = sb1[lane + 32];
#pragma unroll
    for (int k = 0; k < 32; k++) {
        float xk = __shfl_sync(0xffffffffu, x0, k);
        h0 += xk * sW1[lane * 65 + k];
        h1 += xk * sW1[(lane + 32) * 65 + k];
    }
#pragma unroll
    for (int k = 0; k < 32; k++) {
        float xk = __shfl_sync(0xffffffffu, x1, k);
        h0 += xk * sW1[lane * 65 + 32 + k];
        h1 += xk * sW1[(lane + 32) * 65 + 32 + k];
    }
    h0 = fmaxf(h0, 0.f); h1 = fmaxf(h1, 0.f);
    float p = h0 * sW2[lane] + h1 * sW2[lane + 32];
#pragma unroll
    for (int off = 16; off; off >>= 1)
        p += __shfl_xor_sync(0xffffffffu, p, off);
    if (lane == 0) out[row] = p + b2[0];
}

// ---------------- host-side CSR build --------------------------------------------
static void build_csr(const int* ei, int E, int ndst,
                      int* rowptr, int* csr, int* deg, int* cur, int* bsum)
{
    cudaMemsetAsync(deg, 0, (size_t)ndst * sizeof(int), 0);
    hist_kernel<<<(E + 255) / 256, 256>>>(ei, E, deg);
    int nb = (ndst + 1023) / 1024;
    scan1<<<nb, 1024>>>(deg, ndst, rowptr, bsum);
    scan2<<<1, 1024>>>(bsum, nb);
    scan3<<<(ndst + 255) / 256, 256>>>(ndst, rowptr, bsum);
    cudaMemcpyAsync(cur, rowptr, (size_t)ndst * sizeof(int),
                    cudaMemcpyDeviceToDevice, 0);
    scatter_kernel<<<(E + 255) / 256, 256>>>(ei, E, cur, csr);
}

// ---------------- kernel_launch -------------------------------------------------
extern "C" void kernel_launch(void* const* d_in, const int* in_sizes, int n_in,
                              void* d_out, int out_size)
{
    const float* x_acc      = (const float*)d_in[0];
    const float* x_mer      = (const float*)d_in[1];
    const int*   ei_pays    = (const int*)d_in[2];
    const int*   ei_rev     = (const int*)d_in[3];
    const int*   ei_tr      = (const int*)d_in[4];
    const float* projW_acc  = (const float*)d_in[5];
    const float* projb_acc  = (const float*)d_in[6];
    const float* projW_mer  = (const float*)d_in[7];
    const float* projb_mer  = (const float*)d_in[8];
    const float* Wl[3] = {(const float*)d_in[9],  (const float*)d_in[12], (const float*)d_in[15]};
    const float* bl[3] = {(const float*)d_in[10], (const float*)d_in[13], (const float*)d_in[16]};
    const float* Wr[3] = {(const float*)d_in[11], (const float*)d_in[14], (const float*)d_in[17]};
    const float* bng[3] = {(const float*)d_in[18], (const float*)d_in[20], (const float*)d_in[22]};
    const float* bnb[3] = {(const float*)d_in[19], (const float*)d_in[21], (const float*)d_in[23]};
    const float* clfW1 = (const float*)d_in[24];
    const float* clfb1 = (const float*)d_in[25];
    const float* clfW2 = (const float*)d_in[26];
    const float* clfb2 = (const float*)d_in[27];
    float* out = (float*)d_out;

    int nacc = in_sizes[0] / 64;
    int nmer = in_sizes[1] / 32;
    int E    = in_sizes[2] / 2;

    float *xa, *xm, *ya, *ym, *agg, *agg2, *aggm, *stat;
    int *rowptr, *csr, *deg, *cur, *bsum;
    cudaGetSymbolAddress((void**)&xa,     g_xa);
    cudaGetSymbolAddress((void**)&xm,     g_xm);
    cudaGetSymbolAddress((void**)&ya,     g_ya);
    cudaGetSymbolAddress((void**)&ym,     g_ym);
    cudaGetSymbolAddress((void**)&agg,    g_agg);
    cudaGetSymbolAddress((void**)&agg2,   g_agg2);
    cudaGetSymbolAddress((void**)&aggm,   g_aggm);
    cudaGetSymbolAddress((void**)&stat,   g_stat);
    cudaGetSymbolAddress((void**)&rowptr, g_rowptr);
    cudaGetSymbolAddress((void**)&csr,    g_csr);
    cudaGetSymbolAddress((void**)&deg,    g_deg);
    cudaGetSymbolAddress((void**)&cur,    g_cur);
    cudaGetSymbolAddress((void**)&bsum,   g_bsum);

    int* rp[3]  = {rowptr, rowptr + (NACC_MAX + 1), rowptr + 2 * (NACC_MAX + 1)};
    int* cs3[3] = {csr, csr + E_MAX, csr + 2 * E_MAX};
    float* sum_a = stat;        float* sqs_a = stat + 128;
    float* sum_m = stat + 256;  float* sqs_m = stat + 384;

    // --- CSR builds (one per edge type, reused across layers) ---
    build_csr(ei_pays, E, nmer, rp[0], cs3[0], deg, cur, bsum);
    build_csr(ei_rev,  E, nacc, rp[1], cs3[1], deg, cur, bsum);
    build_csr(ei_tr,   E, nacc, rp[2], cs3[2], deg, cur, bsum);

    int agrid = (nacc + 127) / 128;
    int mgrid = (nmer + 127) / 128;

    // --- input projections ---
    mma_gemm<128, 0, false, false><<<agrid, 512>>>(nacc, 64, x_acc, nullptr,
        projW_acc, nullptr, projb_acc, xa, nullptr, nullptr);
    mma_gemm<128, 0, false, false><<<mgrid, 512>>>(nmer, 32, x_mer, nullptr,
        projW_mer, nullptr, projb_mer, xm, nullptr, nullptr);

    int douts[3] = {128, 128, 64};
    for (int L = 0; L < 3; L++) {
        int DO = douts[L];
        int n0 = (L < 2) ? nmer : 0;   // pays dead at L==2

        // --- all aggregations for this layer in one launch ---
        int twarp = n0 + nacc + nacc;
        agg_all<<<(twarp * 32 + 255) / 256, 256>>>(
            n0,   rp[0], cs3[0], xa, aggm,
            nacc, rp[1], cs3[1], xm, agg,
            nacc, rp[2], cs3[2], xa, agg2);

        // (a) pays: acc -> mer; emits merchant BN stats
        if (L < 2) {
            cudaMemsetAsync(sum_m, 0, 256 * sizeof(float), 0);
            mma_gemm<128, 1, false, true><<<mgrid, 512>>>(nmer, 256, aggm, xm,
                Wl[L] + 0 * (size_t)DO * 128, Wr[L] + 0 * (size_t)DO * 128,
                bl[L] + 0 * DO, ym, sum_m, sqs_m);
        }

        // (b) rev: mer -> acc (no stats: not final value yet)
        if (DO == 128)
            mma_gemm<128, 1, false, false><<<agrid, 512>>>(nacc, 256, agg, xa,
                Wl[L] + 1 * (size_t)DO * 128, Wr[L] + 1 * (size_t)DO * 128,
                bl[L] + 1 * DO, ya, nullptr, nullptr);
        else
            mma_gemm<64, 1, false, false><<<agrid, 512>>>(nacc, 256, agg, xa,
                Wl[L] + 1 * (size_t)DO * 128, Wr[L] + 1 * (size_t)DO * 128,
                bl[L] + 1 * DO, ya, nullptr, nullptr);

        // (c) transfer: acc -> acc (HeteroConv +=); emits account BN stats
        cudaMemsetAsync(sum_a, 0, 256 * sizeof(float), 0);
        if (DO == 128)
            mma_gemm<128, 1, true, true><<<agrid, 512>>>(nacc, 256, agg2, xa,
                Wl[L] + 2 * (size_t)DO * 128, Wr[L] + 2 * (size_t)DO * 128,
                bl[L] + 2 * DO, ya, sum_a, sqs_a);
        else
            mma_gemm<64, 1, true, true><<<agrid, 512>>>(nacc, 256, agg2, xa,
                Wl[L] + 2 * (size_t)DO * 128, Wr[L] + 2 * (size_t)DO * 128,
                bl[L] + 2 * DO, ya, sum_a, sqs_a);

        // (d) BN account (+ReLU except last layer)
        bn_apply_kernel<<<2048, 256>>>(ya, xa, nacc, DO, sum_a, sqs_a,
                                       bng[L] + 0 * DO, bnb[L] + 0 * DO, (L < 2) ? 1 : 0);

        // (e) BN merchant (+ReLU); dead at L==2
        if (L < 2) {
            bn_apply_kernel<<<2048, 256>>>(ym, xm, nmer, DO, sum_m, sqs_m,
                                           bng[L] + 1 * DO, bnb[L] + 1 * DO, 1);
        }
    }

    // --- classifier head on accounts ---
    classifier_kernel<<<(nacc + 7) / 8, 256>>>(xa, nacc, clfW1, clfb1, clfW2, clfb2, out);
}